// round 3
// baseline (speedup 1.0000x reference)
#include <cuda_runtime.h>
#include <math.h>

#define NROWS 8192
#define DIM   512

// Scratch (static device globals — allowed; no runtime allocation).
__device__ float g_Q[NROWS * DIM];
__device__ float g_K[NROWS * DIM];
__device__ float g_V[NROWS * DIM];
__device__ float g_A[NROWS * DIM];

// ---------------------------------------------------------------------------
// SGEMM with bias: C[M,512] = A[M,512] @ W[512,512] + b
// BM=128, BN=64, BK=16, 256 threads, 8x4 register tile per thread.
// ---------------------------------------------------------------------------
__global__ __launch_bounds__(256) void sgemm_bias_kernel(
    const float* __restrict__ A, const float* __restrict__ W,
    const float* __restrict__ bias, float* __restrict__ C)
{
    __shared__ float As[16][128];   // As[k][m]  (transposed A tile)
    __shared__ float Ws[16][64];    // Ws[k][n]

    const int tid  = threadIdx.x;          // 0..255
    const int m0   = blockIdx.y * 128;
    const int n0   = blockIdx.x * 64;
    const int trow = tid >> 4;             // 0..15 -> rows trow*8 .. trow*8+7
    const int tcol = tid & 15;             // 0..15 -> cols tcol*4 .. tcol*4+3

    float acc[8][4];
#pragma unroll
    for (int i = 0; i < 8; i++)
#pragma unroll
        for (int j = 0; j < 4; j++) acc[i][j] = 0.f;

    const int wk  = tid >> 4;   // 0..15  (k row of W tile)
    const int wn4 = tid & 15;   // 0..15  (float4 col of W tile)

    for (int k0 = 0; k0 < 512; k0 += 16) {
        // Load A tile: 128x16 floats = 512 float4, 2 per thread.
#pragma unroll
        for (int l = 0; l < 2; l++) {
            int f    = tid + l * 256;
            int arow = f >> 2;
            int kq   = f & 3;
            float4 va = *(const float4*)(A + (size_t)(m0 + arow) * 512 + k0 + kq * 4);
            As[kq * 4 + 0][arow] = va.x;
            As[kq * 4 + 1][arow] = va.y;
            As[kq * 4 + 2][arow] = va.z;
            As[kq * 4 + 3][arow] = va.w;
        }
        // Load W tile: 16x64 floats = 256 float4, 1 per thread.
        {
            float4 vw = *(const float4*)(W + (size_t)(k0 + wk) * 512 + n0 + wn4 * 4);
            *(float4*)&Ws[wk][wn4 * 4] = vw;
        }
        __syncthreads();

#pragma unroll
        for (int kk = 0; kk < 16; kk++) {
            float4 w4 = *(float4*)&Ws[kk][tcol * 4];
            float4 a0 = *(float4*)&As[kk][trow * 8];
            float4 a1 = *(float4*)&As[kk][trow * 8 + 4];
            float a[8] = {a0.x, a0.y, a0.z, a0.w, a1.x, a1.y, a1.z, a1.w};
            float w[4] = {w4.x, w4.y, w4.z, w4.w};
#pragma unroll
            for (int i = 0; i < 8; i++)
#pragma unroll
                for (int j = 0; j < 4; j++)
                    acc[i][j] = fmaf(a[i], w[j], acc[i][j]);
        }
        __syncthreads();
    }

    float4 b4 = *(const float4*)(bias + n0 + tcol * 4);
#pragma unroll
    for (int i = 0; i < 8; i++) {
        float4 o;
        o.x = acc[i][0] + b4.x;
        o.y = acc[i][1] + b4.y;
        o.z = acc[i][2] + b4.z;
        o.w = acc[i][3] + b4.w;
        *(float4*)(C + (size_t)(m0 + trow * 8 + i) * 512 + n0 + tcol * 4) = o;
    }
}

// ---------------------------------------------------------------------------
// Segment-masked attention, one CTA (4 warps) per query row.
// Deterministic: j scanned in ascending order via ballot compaction.
// Online softmax per warp, cross-warp merge in smem.
// ---------------------------------------------------------------------------
__global__ __launch_bounds__(128) void attn_kernel(
    const float* __restrict__ Q, const float* __restrict__ K,
    const float* __restrict__ V, const int* __restrict__ labels,
    float* __restrict__ Aout)
{
    const int i    = blockIdx.x;
    const int tid  = threadIdx.x;       // 0..127
    const int warp = tid >> 5;
    const int lane = tid & 31;

    const int g = labels[i];
    if (g < 0) {
        // Row stays zero (reference: where(valid, out, 0))
        ((float4*)(Aout + (size_t)i * 512))[tid] = make_float4(0.f, 0.f, 0.f, 0.f);
        return;
    }

    const float scale = 0.04419417382415922f;  // 1/sqrt(512)
    const float4* Q4 = (const float4*)Q;
    const float4* K4 = (const float4*)K;
    const float4* V4 = (const float4*)V;

    // Each lane owns float4 slots: lane + 32*b, b=0..3 (16 floats of the row).
    float4 q[4], acc[4];
#pragma unroll
    for (int b = 0; b < 4; b++) {
        q[b]   = Q4[(size_t)i * 128 + lane + 32 * b];
        acc[b] = make_float4(0.f, 0.f, 0.f, 0.f);
    }
    float m = -INFINITY, l = 0.f;

    // 8192 labels in 256 chunks of 32; warp w handles chunks w, w+4, ...
    for (int c = warp; c < 256; c += 4) {
        const int j0  = c * 32;
        const int lab = labels[j0 + lane];
        unsigned mask = __ballot_sync(0xffffffffu, lab == g);
        while (mask) {
            const int bit = __ffs(mask) - 1;
            mask &= mask - 1;
            const int j = j0 + bit;

            const float4 k0 = K4[(size_t)j * 128 + lane];
            const float4 k1 = K4[(size_t)j * 128 + lane + 32];
            const float4 k2 = K4[(size_t)j * 128 + lane + 64];
            const float4 k3 = K4[(size_t)j * 128 + lane + 96];
            float s = q[0].x * k0.x + q[0].y * k0.y + q[0].z * k0.z + q[0].w * k0.w
                    + q[1].x * k1.x + q[1].y * k1.y + q[1].z * k1.z + q[1].w * k1.w
                    + q[2].x * k2.x + q[2].y * k2.y + q[2].z * k2.z + q[2].w * k2.w
                    + q[3].x * k3.x + q[3].y * k3.y + q[3].z * k3.z + q[3].w * k3.w;
#pragma unroll
            for (int off = 16; off > 0; off >>= 1)
                s += __shfl_xor_sync(0xffffffffu, s, off);
            s *= scale;

            const float mnew = fmaxf(m, s);
            const float corr = __expf(m - mnew);   // exp(-inf)=0 on first hit
            const float p    = __expf(s - mnew);
            l = l * corr + p;
            m = mnew;

            const float4 v0 = V4[(size_t)j * 128 + lane];
            const float4 v1 = V4[(size_t)j * 128 + lane + 32];
            const float4 v2 = V4[(size_t)j * 128 + lane + 64];
            const float4 v3 = V4[(size_t)j * 128 + lane + 96];
            acc[0].x = acc[0].x * corr + p * v0.x;  acc[0].y = acc[0].y * corr + p * v0.y;
            acc[0].z = acc[0].z * corr + p * v0.z;  acc[0].w = acc[0].w * corr + p * v0.w;
            acc[1].x = acc[1].x * corr + p * v1.x;  acc[1].y = acc[1].y * corr + p * v1.y;
            acc[1].z = acc[1].z * corr + p * v1.z;  acc[1].w = acc[1].w * corr + p * v1.w;
            acc[2].x = acc[2].x * corr + p * v2.x;  acc[2].y = acc[2].y * corr + p * v2.y;
            acc[2].z = acc[2].z * corr + p * v2.z;  acc[2].w = acc[2].w * corr + p * v2.w;
            acc[3].x = acc[3].x * corr + p * v3.x;  acc[3].y = acc[3].y * corr + p * v3.y;
            acc[3].z = acc[3].z * corr + p * v3.z;  acc[3].w = acc[3].w * corr + p * v3.w;
        }
    }

    // Cross-warp merge.
    __shared__ float  sm[4], sl[4];
    __shared__ float4 swacc[4][128];
    if (lane == 0) { sm[warp] = m; sl[warp] = l; }
    __syncthreads();

    const float M = fmaxf(fmaxf(sm[0], sm[1]), fmaxf(sm[2], sm[3]));  // finite: row attends to itself
    const float L = sl[0] * __expf(sm[0] - M) + sl[1] * __expf(sm[1] - M)
                  + sl[2] * __expf(sm[2] - M) + sl[3] * __expf(sm[3] - M);
    const float ws = __expf(m - M);   // this warp's rescale (0 if warp saw nothing)
#pragma unroll
    for (int b = 0; b < 4; b++) {
        float4 t;
        t.x = acc[b].x * ws; t.y = acc[b].y * ws; t.z = acc[b].z * ws; t.w = acc[b].w * ws;
        swacc[warp][lane + 32 * b] = t;
    }
    __syncthreads();

    const float invL = 1.0f / L;
    float4 r = swacc[0][tid];
    float4 r1 = swacc[1][tid], r2 = swacc[2][tid], r3 = swacc[3][tid];
    r.x = (r.x + r1.x + r2.x + r3.x) * invL;
    r.y = (r.y + r1.y + r2.y + r3.y) * invL;
    r.z = (r.z + r1.z + r2.z + r3.z) * invL;
    r.w = (r.w + r1.w + r2.w + r3.w) * invL;
    ((float4*)(Aout + (size_t)i * 512))[tid] = r;
}

// ---------------------------------------------------------------------------
extern "C" void kernel_launch(void* const* d_in, const int* in_sizes, int n_in,
                              void* d_out, int out_size)
{
    const float* x      = (const float*)d_in[0];
    const int*   labels = (const int*)  d_in[1];
    const float* Wq     = (const float*)d_in[2];
    const float* bq     = (const float*)d_in[3];
    const float* Wk     = (const float*)d_in[4];
    const float* bk     = (const float*)d_in[5];
    const float* Wv     = (const float*)d_in[6];
    const float* bv     = (const float*)d_in[7];
    const float* Wo     = (const float*)d_in[8];
    const float* bo     = (const float*)d_in[9];
    float* out = (float*)d_out;

    float *Qp, *Kp, *Vp, *Ap;
    cudaGetSymbolAddress((void**)&Qp, g_Q);
    cudaGetSymbolAddress((void**)&Kp, g_K);
    cudaGetSymbolAddress((void**)&Vp, g_V);
    cudaGetSymbolAddress((void**)&Ap, g_A);

    dim3 gg(512 / 64, NROWS / 128);   // (8, 64)
    sgemm_bias_kernel<<<gg, 256>>>(x, Wq, bq, Qp);
    sgemm_bias_kernel<<<gg, 256>>>(x, Wk, bk, Kp);
    sgemm_bias_kernel<<<gg, 256>>>(x, Wv, bv, Vp);
    attn_kernel<<<NROWS, 128>>>(Qp, Kp, Vp, labels, Ap);
    sgemm_bias_kernel<<<gg, 256>>>(Ap, Wo, bo, out);
}

// round 6
// speedup vs baseline: 1.5772x; 1.5772x over previous
#include <cuda_runtime.h>
#include <cuda_bf16.h>
#include <math.h>
#include <stdint.h>

#define NROWS 8192
#define DIM   512

// ---------------------------------------------------------------------------
// Scratch (static device globals — no runtime allocation).
// ---------------------------------------------------------------------------
__device__ float g_Q[NROWS * DIM];
__device__ float g_K[NROWS * DIM];
__device__ float g_V[NROWS * DIM];
__device__ float g_A[NROWS * DIM];

__device__ __nv_bfloat16 g_xhi[NROWS * DIM];
__device__ __nv_bfloat16 g_xlo[NROWS * DIM];
__device__ __nv_bfloat16 g_ahi[NROWS * DIM];
__device__ __nv_bfloat16 g_alo[NROWS * DIM];
// Transposed weights, bf16 hi/lo: [N][K] layout (B operand). 4 matrices.
__device__ __nv_bfloat16 g_whi[4][DIM * DIM];
__device__ __nv_bfloat16 g_wlo[4][DIM * DIM];

// ---------------------------------------------------------------------------
// Helpers (baseline sm_103 ISA only: ldmatrix / mma.sync / cp.async)
// ---------------------------------------------------------------------------
__device__ __forceinline__ uint32_t smem_to_u32(const void* p) {
    uint32_t a;
    asm("{ .reg .u64 t; cvta.to.shared.u64 t, %1; cvt.u32.u64 %0, t; }" : "=r"(a) : "l"(p));
    return a;
}

__device__ __forceinline__ void cp_async16(uint32_t s, const void* g) {
    asm volatile("cp.async.cg.shared.global [%0], [%1], 16;" :: "r"(s), "l"(g));
}
__device__ __forceinline__ void cp_commit() {
    asm volatile("cp.async.commit_group;" ::: "memory");
}
__device__ __forceinline__ void cp_wait1() {
    asm volatile("cp.async.wait_group 1;" ::: "memory");
}
__device__ __forceinline__ void cp_wait0() {
    asm volatile("cp.async.wait_group 0;" ::: "memory");
}

__device__ __forceinline__ void ldsm_x4(uint32_t* r, uint32_t addr) {
    asm volatile("ldmatrix.sync.aligned.m8n8.x4.shared.b16 {%0,%1,%2,%3}, [%4];"
                 : "=r"(r[0]), "=r"(r[1]), "=r"(r[2]), "=r"(r[3]) : "r"(addr));
}

__device__ __forceinline__ void mma16816(float* d, const uint32_t* a, uint32_t b0, uint32_t b1) {
    asm volatile(
        "mma.sync.aligned.m16n8k16.row.col.f32.bf16.bf16.f32 "
        "{%0,%1,%2,%3}, {%4,%5,%6,%7}, {%8,%9}, {%0,%1,%2,%3};"
        : "+f"(d[0]), "+f"(d[1]), "+f"(d[2]), "+f"(d[3])
        : "r"(a[0]), "r"(a[1]), "r"(a[2]), "r"(a[3]), "r"(b0), "r"(b1));
}

// ---------------------------------------------------------------------------
// fp32 -> bf16 hi/lo split (elementwise)
// ---------------------------------------------------------------------------
__global__ __launch_bounds__(256) void split_kernel(
    const float* __restrict__ x, __nv_bfloat16* __restrict__ hi,
    __nv_bfloat16* __restrict__ lo, int n)
{
    int i = blockIdx.x * 256 + threadIdx.x;
    if (i < n) {
        float v = x[i];
        __nv_bfloat16 h = __float2bfloat16_rn(v);
        float r = v - __bfloat162float(h);
        hi[i] = h;
        lo[i] = __float2bfloat16_rn(r);
    }
}

// ---------------------------------------------------------------------------
// W [K=512][N=512] row-major -> transposed bf16 hi/lo [N][K]
// ---------------------------------------------------------------------------
__global__ __launch_bounds__(256) void wsplit_t_kernel(
    const float* __restrict__ W, __nv_bfloat16* __restrict__ hi, __nv_bfloat16* __restrict__ lo)
{
    __shared__ float t[32][33];
    const int tx = threadIdx.x & 31;
    const int ty = threadIdx.x >> 5;   // 0..7
    const int k0 = blockIdx.y * 32;
    const int n0 = blockIdx.x * 32;
#pragma unroll
    for (int i = 0; i < 32; i += 8)
        t[ty + i][tx] = W[(size_t)(k0 + ty + i) * 512 + n0 + tx];
    __syncthreads();
#pragma unroll
    for (int i = 0; i < 32; i += 8) {
        float v = t[tx][ty + i];
        __nv_bfloat16 h = __float2bfloat16_rn(v);
        float r = v - __bfloat162float(h);
        size_t idx = (size_t)(n0 + ty + i) * 512 + k0 + tx;
        hi[idx] = h;
        lo[idx] = __float2bfloat16_rn(r);
    }
}

// ---------------------------------------------------------------------------
// HMMA GEMM: C[8192,512] = (Ahi+Alo)[8192,512] @ (Bhi+Blo [N][K])^T + bias
// CTA tile 128x128, 8 warps (2 in M x 4 in N), warp tile 64x32.
// K chunks of 64, cp.async double buffer. 3 terms: hh + hl + lh.
// smem tiles: row stride 144B (72 bf16) -> conflict-free ldmatrix.
// ---------------------------------------------------------------------------
static constexpr int TILE_BYTES = 128 * 144;       // 18432
static constexpr int STAGE_B    = 4 * TILE_BYTES;  // Ah, Al, Bh, Bl = 73728
static constexpr int GEMM_SMEM_TOTAL = 2 * STAGE_B;  // 147456

__device__ __forceinline__ void load_tile(
    uint32_t sdst, const __nv_bfloat16* __restrict__ src, int rowbase, int kc, int tid)
{
    const char* s = (const char*)(src + (size_t)rowbase * 512) + kc * 128;
#pragma unroll
    for (int i = 0; i < 4; i++) {
        int f   = tid + i * 256;
        int row = f >> 3;
        int c   = f & 7;
        cp_async16(sdst + row * 144 + c * 16, s + (size_t)row * 1024 + c * 16);
    }
}

__global__ __launch_bounds__(256)
void gemm_mma_kernel(const __nv_bfloat16* __restrict__ Ahi, const __nv_bfloat16* __restrict__ Alo,
                     const __nv_bfloat16* __restrict__ Bhi, const __nv_bfloat16* __restrict__ Blo,
                     const float* __restrict__ bias, float* __restrict__ C)
{
    extern __shared__ char smem_c[];
    const uint32_t sb = smem_to_u32(smem_c);

    const int tid  = threadIdx.x;
    const int wid  = tid >> 5;
    const int lane = tid & 31;
    const int m0 = blockIdx.y * 128;
    const int n0 = blockIdx.x * 128;
    const int wm = (wid & 1) * 64;    // 2 warps in M
    const int wn = (wid >> 1) * 32;   // 4 warps in N

    float acc[4][4][4];
#pragma unroll
    for (int im = 0; im < 4; im++)
#pragma unroll
        for (int in = 0; in < 4; in++)
#pragma unroll
            for (int e = 0; e < 4; e++) acc[im][in][e] = 0.f;

    // Prefetch chunk 0
    {
        uint32_t st = sb;
        load_tile(st + 0 * TILE_BYTES, Ahi, m0, 0, tid);
        load_tile(st + 1 * TILE_BYTES, Alo, m0, 0, tid);
        load_tile(st + 2 * TILE_BYTES, Bhi, n0, 0, tid);
        load_tile(st + 3 * TILE_BYTES, Blo, n0, 0, tid);
        cp_commit();
    }

    const int rowA  = wm + (lane & 15);
    const int rowB  = wn + (lane & 15);
    const int khalf = (lane >> 4) * 8;   // element offset

    for (int kc = 0; kc < 8; kc++) {
        const uint32_t cur = sb + (uint32_t)(kc & 1) * STAGE_B;
        if (kc < 7) {
            uint32_t nxt = sb + (uint32_t)((kc + 1) & 1) * STAGE_B;
            load_tile(nxt + 0 * TILE_BYTES, Ahi, m0, kc + 1, tid);
            load_tile(nxt + 1 * TILE_BYTES, Alo, m0, kc + 1, tid);
            load_tile(nxt + 2 * TILE_BYTES, Bhi, n0, kc + 1, tid);
            load_tile(nxt + 3 * TILE_BYTES, Blo, n0, kc + 1, tid);
            cp_commit();
            cp_wait1();
        } else {
            cp_wait0();
        }
        __syncthreads();

        const uint32_t sAh = cur + 0 * TILE_BYTES;
        const uint32_t sAl = cur + 1 * TILE_BYTES;
        const uint32_t sBh = cur + 2 * TILE_BYTES;
        const uint32_t sBl = cur + 3 * TILE_BYTES;

#pragma unroll
        for (int ks = 0; ks < 4; ks++) {
            const int ke = ks * 16 + khalf;  // bf16 element offset in row
            uint32_t ah[4][4], al[4][4], bh[2][4], bl[2][4];
#pragma unroll
            for (int im = 0; im < 4; im++) {
                ldsm_x4(ah[im], sAh + ((rowA + im * 16) * 72 + ke) * 2);
                ldsm_x4(al[im], sAl + ((rowA + im * 16) * 72 + ke) * 2);
            }
#pragma unroll
            for (int ib = 0; ib < 2; ib++) {
                ldsm_x4(bh[ib], sBh + ((rowB + ib * 16) * 72 + ke) * 2);
                ldsm_x4(bl[ib], sBl + ((rowB + ib * 16) * 72 + ke) * 2);
            }
#pragma unroll
            for (int im = 0; im < 4; im++) {
#pragma unroll
                for (int in = 0; in < 4; in++) {
                    const int ib  = in >> 1;
                    const int sel = in & 1;
                    mma16816(acc[im][in], ah[im], bh[ib][sel], bh[ib][sel + 2]);  // hi*hi
                    mma16816(acc[im][in], ah[im], bl[ib][sel], bl[ib][sel + 2]);  // hi*lo
                    mma16816(acc[im][in], al[im], bh[ib][sel], bh[ib][sel + 2]);  // lo*hi
                }
            }
        }
        __syncthreads();
    }

    // Epilogue: bias + store
    const int gid = lane >> 2;   // 0..7
    const int tg  = lane & 3;    // 0..3
#pragma unroll
    for (int im = 0; im < 4; im++) {
        const int r0 = m0 + wm + im * 16 + gid;
        const int r1 = r0 + 8;
#pragma unroll
        for (int in = 0; in < 4; in++) {
            const int col = n0 + wn + in * 8 + tg * 2;
            const float b0 = bias[col], b1 = bias[col + 1];
            float2 v0 = make_float2(acc[im][in][0] + b0, acc[im][in][1] + b1);
            float2 v1 = make_float2(acc[im][in][2] + b0, acc[im][in][3] + b1);
            *(float2*)(C + (size_t)r0 * 512 + col) = v0;
            *(float2*)(C + (size_t)r1 * 512 + col) = v1;
        }
    }
}

// ---------------------------------------------------------------------------
// Segment-masked attention, one CTA (4 warps) per query row (R3, passing).
// ---------------------------------------------------------------------------
__global__ __launch_bounds__(128) void attn_kernel(
    const float* __restrict__ Q, const float* __restrict__ K,
    const float* __restrict__ V, const int* __restrict__ labels,
    float* __restrict__ Aout)
{
    const int i    = blockIdx.x;
    const int tid  = threadIdx.x;
    const int warp = tid >> 5;
    const int lane = tid & 31;

    const int g = labels[i];
    if (g < 0) {
        ((float4*)(Aout + (size_t)i * 512))[tid] = make_float4(0.f, 0.f, 0.f, 0.f);
        return;
    }

    const float scale = 0.04419417382415922f;  // 1/sqrt(512)
    const float4* Q4 = (const float4*)Q;
    const float4* K4 = (const float4*)K;
    const float4* V4 = (const float4*)V;

    float4 q[4], acc[4];
#pragma unroll
    for (int b = 0; b < 4; b++) {
        q[b]   = Q4[(size_t)i * 128 + lane + 32 * b];
        acc[b] = make_float4(0.f, 0.f, 0.f, 0.f);
    }
    float m = -INFINITY, l = 0.f;

    for (int c = warp; c < 256; c += 4) {
        const int j0  = c * 32;
        const int lab = labels[j0 + lane];
        unsigned mask = __ballot_sync(0xffffffffu, lab == g);
        while (mask) {
            const int bit = __ffs(mask) - 1;
            mask &= mask - 1;
            const int j = j0 + bit;

            const float4 k0 = K4[(size_t)j * 128 + lane];
            const float4 k1 = K4[(size_t)j * 128 + lane + 32];
            const float4 k2 = K4[(size_t)j * 128 + lane + 64];
            const float4 k3 = K4[(size_t)j * 128 + lane + 96];
            float s = q[0].x * k0.x + q[0].y * k0.y + q[0].z * k0.z + q[0].w * k0.w
                    + q[1].x * k1.x + q[1].y * k1.y + q[1].z * k1.z + q[1].w * k1.w
                    + q[2].x * k2.x + q[2].y * k2.y + q[2].z * k2.z + q[2].w * k2.w
                    + q[3].x * k3.x + q[3].y * k3.y + q[3].z * k3.z + q[3].w * k3.w;
#pragma unroll
            for (int off = 16; off > 0; off >>= 1)
                s += __shfl_xor_sync(0xffffffffu, s, off);
            s *= scale;

            const float mnew = fmaxf(m, s);
            const float corr = __expf(m - mnew);
            const float p    = __expf(s - mnew);
            l = l * corr + p;
            m = mnew;

            const float4 v0 = V4[(size_t)j * 128 + lane];
            const float4 v1 = V4[(size_t)j * 128 + lane + 32];
            const float4 v2 = V4[(size_t)j * 128 + lane + 64];
            const float4 v3 = V4[(size_t)j * 128 + lane + 96];
            acc[0].x = acc[0].x * corr + p * v0.x;  acc[0].y = acc[0].y * corr + p * v0.y;
            acc[0].z = acc[0].z * corr + p * v0.z;  acc[0].w = acc[0].w * corr + p * v0.w;
            acc[1].x = acc[1].x * corr + p * v1.x;  acc[1].y = acc[1].y * corr + p * v1.y;
            acc[1].z = acc[1].z * corr + p * v1.z;  acc[1].w = acc[1].w * corr + p * v1.w;
            acc[2].x = acc[2].x * corr + p * v2.x;  acc[2].y = acc[2].y * corr + p * v2.y;
            acc[2].z = acc[2].z * corr + p * v2.z;  acc[2].w = acc[2].w * corr + p * v2.w;
            acc[3].x = acc[3].x * corr + p * v3.x;  acc[3].y = acc[3].y * corr + p * v3.y;
            acc[3].z = acc[3].z * corr + p * v3.z;  acc[3].w = acc[3].w * corr + p * v3.w;
        }
    }

    __shared__ float  sm[4], sl[4];
    __shared__ float4 swacc[4][128];
    if (lane == 0) { sm[warp] = m; sl[warp] = l; }
    __syncthreads();

    const float M = fmaxf(fmaxf(sm[0], sm[1]), fmaxf(sm[2], sm[3]));
    const float L = sl[0] * __expf(sm[0] - M) + sl[1] * __expf(sm[1] - M)
                  + sl[2] * __expf(sm[2] - M) + sl[3] * __expf(sm[3] - M);
    const float ws = __expf(m - M);
#pragma unroll
    for (int b = 0; b < 4; b++) {
        float4 t;
        t.x = acc[b].x * ws; t.y = acc[b].y * ws; t.z = acc[b].z * ws; t.w = acc[b].w * ws;
        swacc[warp][lane + 32 * b] = t;
    }
    __syncthreads();

    const float invL = 1.0f / L;
    float4 r  = swacc[0][tid];
    float4 r1 = swacc[1][tid], r2 = swacc[2][tid], r3 = swacc[3][tid];
    r.x = (r.x + r1.x + r2.x + r3.x) * invL;
    r.y = (r.y + r1.y + r2.y + r3.y) * invL;
    r.z = (r.z + r1.z + r2.z + r3.z) * invL;
    r.w = (r.w + r1.w + r2.w + r3.w) * invL;
    ((float4*)(Aout + (size_t)i * 512))[tid] = r;
}

// ---------------------------------------------------------------------------
extern "C" void kernel_launch(void* const* d_in, const int* in_sizes, int n_in,
                              void* d_out, int out_size)
{
    const float* x      = (const float*)d_in[0];
    const int*   labels = (const int*)  d_in[1];
    const float* Wq     = (const float*)d_in[2];
    const float* bq     = (const float*)d_in[3];
    const float* Wk     = (const float*)d_in[4];
    const float* bk     = (const float*)d_in[5];
    const float* Wv     = (const float*)d_in[6];
    const float* bv     = (const float*)d_in[7];
    const float* Wo     = (const float*)d_in[8];
    const float* bo     = (const float*)d_in[9];
    float* out = (float*)d_out;

    float *Qp, *Kp, *Vp, *Ap;
    cudaGetSymbolAddress((void**)&Qp, g_Q);
    cudaGetSymbolAddress((void**)&Kp, g_K);
    cudaGetSymbolAddress((void**)&Vp, g_V);
    cudaGetSymbolAddress((void**)&Ap, g_A);
    __nv_bfloat16 *xhi, *xlo, *ahi, *alo, *whi, *wlo;
    cudaGetSymbolAddress((void**)&xhi, g_xhi);
    cudaGetSymbolAddress((void**)&xlo, g_xlo);
    cudaGetSymbolAddress((void**)&ahi, g_ahi);
    cudaGetSymbolAddress((void**)&alo, g_alo);
    cudaGetSymbolAddress((void**)&whi, g_whi);
    cudaGetSymbolAddress((void**)&wlo, g_wlo);

    cudaFuncSetAttribute(gemm_mma_kernel, cudaFuncAttributeMaxDynamicSharedMemorySize,
                         GEMM_SMEM_TOTAL);

    const int nelem = NROWS * DIM;
    split_kernel<<<(nelem + 255) / 256, 256>>>(x, xhi, xlo, nelem);

    dim3 wgrid(16, 16);
    wsplit_t_kernel<<<wgrid, 256>>>(Wq, whi + 0 * DIM * DIM, wlo + 0 * DIM * DIM);
    wsplit_t_kernel<<<wgrid, 256>>>(Wk, whi + 1 * DIM * DIM, wlo + 1 * DIM * DIM);
    wsplit_t_kernel<<<wgrid, 256>>>(Wv, whi + 2 * DIM * DIM, wlo + 2 * DIM * DIM);
    wsplit_t_kernel<<<wgrid, 256>>>(Wo, whi + 3 * DIM * DIM, wlo + 3 * DIM * DIM);

    dim3 ggrid(DIM / 128, NROWS / 128);   // (4, 64)
    gemm_mma_kernel<<<ggrid, 256, GEMM_SMEM_TOTAL>>>(xhi, xlo, whi + 0 * DIM * DIM, wlo + 0 * DIM * DIM, bq, Qp);
    gemm_mma_kernel<<<ggrid, 256, GEMM_SMEM_TOTAL>>>(xhi, xlo, whi + 1 * DIM * DIM, wlo + 1 * DIM * DIM, bk, Kp);
    gemm_mma_kernel<<<ggrid, 256, GEMM_SMEM_TOTAL>>>(xhi, xlo, whi + 2 * DIM * DIM, wlo + 2 * DIM * DIM, bv, Vp);

    attn_kernel<<<NROWS, 128>>>(Qp, Kp, Vp, labels, Ap);

    split_kernel<<<(nelem + 255) / 256, 256>>>(Ap, ahi, alo, nelem);
    gemm_mma_kernel<<<ggrid, 256, GEMM_SMEM_TOTAL>>>(ahi, alo, whi + 3 * DIM * DIM, wlo + 3 * DIM * DIM, bo, out);
}